// round 14
// baseline (speedup 1.0000x reference)
#include <cuda_runtime.h>
#include <cuda_fp16.h>

#define THREADS 384
#define PTS_PER_TILE 384

typedef unsigned int u32;

// ---------------- packed weight image (global + SMEM, same layout) ----------
#define PW_L0    0          // 4 kc  -> 16384 B
#define PW_L1    16384      // 8 kc  -> 32768 B
#define PW_L2    49152      // 8 kc  -> 32768 B
#define PW_L3    81920      // 12 kc -> 49152 B
#define PBH_OFF  131072     // b0,b1,b2 as fp16
#define PB3_OFF  132096     // b3 f32
#define PWO_OFF  132608     // 384 f32
#define PBO_OFF  134144     // 3 f32 (+pad)
#define COPY_BYTES 134160
#define COPY_U4  (COPY_BYTES/16)

// SMEM extras
#define SM_FEAT  COPY_BYTES                      // 384 rows x 144 B (64 fp16 + pad)
#define FEAT_STRIDE 72                           // halves per row
#define SM_RET   (SM_FEAT + PTS_PER_TILE*144)
#define SMEM_BYTES (SM_RET + PTS_PER_TILE*16)    // 195600 B

__device__ __align__(16) unsigned char g_wpack[COPY_BYTES];   // packed weights image

static __device__ __forceinline__ u32 pkh2(float lo, float hi) {
    __half2 h = __floats2half2_rn(lo, hi);
    return *(u32*)&h;
}
static __device__ __forceinline__ u32 relu_bias_h2(u32 c, u32 b) {
    __half2 z = __floats2half2_rn(0.0f, 0.0f);
    __half2 r = __hmax2(__hadd2(*(__half2*)&c, *(__half2*)&b), z);
    return *(u32*)&r;
}

static __device__ __forceinline__ void mma_h16(u32 c[2], const u32 a[4], u32 b0, u32 b1) {
    asm("mma.sync.aligned.m16n8k16.row.col.f16.f16.f16.f16 "
        "{%0,%1}, {%2,%3,%4,%5}, {%6,%7}, {%0,%1};"
        : "+r"(c[0]), "+r"(c[1])
        : "r"(a[0]), "r"(a[1]), "r"(a[2]), "r"(a[3]), "r"(b0), "r"(b1));
}

// ---------------------------------------------------------------------------
// Kernel: pack weights into fp16 B-fragment order.
// ---------------------------------------------------------------------------
__global__ void prep_weights(const float* __restrict__ w0, const float* __restrict__ w1,
                             const float* __restrict__ w2, const float* __restrict__ w3,
                             const float* __restrict__ b0, const float* __restrict__ b1,
                             const float* __restrict__ b2, const float* __restrict__ b3,
                             const float* __restrict__ wo, const float* __restrict__ bo) {
    int t = blockIdx.x * 256 + threadIdx.x;
    if (t < 16384) {
        const float* w; int Kreal, base, s;
        if      (t < 2048)  { w = w0; Kreal = 63;  base = PW_L0; s = t; }
        else if (t < 6144)  { w = w1; Kreal = 128; base = PW_L1; s = t - 2048; }
        else if (t < 10240) { w = w2; Kreal = 128; base = PW_L2; s = t - 6144; }
        else                { w = w3; Kreal = 191; base = PW_L3; s = t - 10240; }
        int lane = s & 31, n = (s >> 5) & 15, kc = s >> 9;
        int k0 = kc * 16 + (lane & 3) * 2;
        int o  = n * 8 + (lane >> 2);
        float v00 = (k0     < Kreal) ? __ldg(w + (k0    ) * 128 + o) : 0.0f;
        float v01 = (k0 + 1 < Kreal) ? __ldg(w + (k0 + 1) * 128 + o) : 0.0f;
        float v10 = (k0 + 8 < Kreal) ? __ldg(w + (k0 + 8) * 128 + o) : 0.0f;
        float v11 = (k0 + 9 < Kreal) ? __ldg(w + (k0 + 9) * 128 + o) : 0.0f;
        ((uint2*)(g_wpack + base))[s] = make_uint2(pkh2(v00, v01), pkh2(v10, v11));
    } else if (t < 16768) {
        int j = t - 16384;
        const float* bs = (j < 128) ? b0 : (j < 256) ? b1 : b2;
        *(__half*)(g_wpack + PBH_OFF + j * 2) = __float2half_rn(__ldg(bs + (j & 127)));
    } else if (t < 16896) {
        int j = t - 16768;
        *(float*)(g_wpack + PB3_OFF + j * 4) = __ldg(b3 + j);
    } else if (t < 17280) {
        int j = t - 16896;
        *(float*)(g_wpack + PWO_OFF + j * 4) = __ldg(wo + j);
    } else if (t < 17283) {
        int j = t - 17280;
        *(float*)(g_wpack + PBO_OFF + j * 4) = __ldg(bo + j);
    }
}

// ---------------------------------------------------------------------------
// Epilogue: C frags + bias(fp16) -> relu -> next-layer A frags (register-only)
// ---------------------------------------------------------------------------
static __device__ __forceinline__ void epi_h2(const u32 c[2][16][2],
                                              const __half* __restrict__ bh,
                                              int t4, u32 A[2][8][4]) {
#pragma unroll
    for (int mt = 0; mt < 2; mt++)
#pragma unroll
        for (int n = 0; n < 16; n++) {
            u32 bb = *(const u32*)(bh + 8 * n + 2 * t4);
            A[mt][n >> 1][(n & 1) * 2 + 0] = relu_bias_h2(c[mt][n][0], bb);
            A[mt][n >> 1][(n & 1) * 2 + 1] = relu_bias_h2(c[mt][n][1], bb);
        }
}

template <int CH>
static __device__ __forceinline__ void run_layer(u32 c[2][16][2],
                                                 const u32 A[2][CH][4],
                                                 const uint2* __restrict__ W, int lane) {
#pragma unroll
    for (int mt = 0; mt < 2; mt++)
#pragma unroll
        for (int n = 0; n < 16; n++) { c[mt][n][0] = 0u; c[mt][n][1] = 0u; }
#pragma unroll
    for (int kc = 0; kc < CH; kc++)
#pragma unroll
        for (int n = 0; n < 16; n++) {
            uint2 b = W[(kc * 16 + n) * 32 + lane];
            mma_h16(c[0][n], A[0][kc], b.x, b.y);
            mma_h16(c[1][n], A[1][kc], b.x, b.y);
        }
}

// ---------------------------------------------------------------------------
// Main fused persistent kernel: 384 threads = 12 warps, 32 points/warp/tile.
// Gradient is computed inline from the raw grid (L2-resident, 67 MB).
// No CTA barriers in the tile loop — all SMEM deps are warp-local.
// ---------------------------------------------------------------------------
__global__ void __launch_bounds__(THREADS, 1)
main_kernel(const float* __restrict__ x, const float* __restrict__ grid,
            float* __restrict__ out, int B, int ntiles) {
    extern __shared__ unsigned char smem[];
    int tid = threadIdx.x;
    int lane = tid & 31, wp = tid >> 5;
    int t4 = lane & 3, lr = lane >> 2;

    // ---- one-time weight image copy L2 -> SMEM ----
    {
        const uint4* s = (const uint4*)g_wpack;
        uint4* d = (uint4*)smem;
#pragma unroll 4
        for (int i = tid; i < COPY_U4; i += THREADS) d[i] = s[i];
    }
    __syncthreads();

    const __half* FS = (const __half*)(smem + SM_FEAT);
    const __half* BH = (const __half*)(smem + PBH_OFF);
    const uint2* W0 = (const uint2*)(smem + PW_L0);
    const uint2* W1 = (const uint2*)(smem + PW_L1);
    const uint2* W2 = (const uint2*)(smem + PW_L2);
    const uint2* W3 = (const uint2*)(smem + PW_L3);
    int row0 = 32 * wp + lr;      // m-tile 0 base row

    for (int tile = blockIdx.x; tile < ntiles; tile += gridDim.x) {
        int gi = tile * PTS_PER_TILE + tid;
        int gc = min(gi, B - 1);
        float px = __ldg(x + 3 * gc), py = __ldg(x + 3 * gc + 1), pz = __ldg(x + 3 * gc + 2);

        // ---- trilinear + inline gradient (exact fp32) -> RET smem ----
        {
            float fx = (px + 1.0f) * 127.5f, fy = (py + 1.0f) * 127.5f, fz = (pz + 1.0f) * 127.5f;
            float flx = floorf(fx), fly = floorf(fy), flz = floorf(fz);
            float xd = fx - flx, yd = fy - fly, zd = fz - flz;
            float xw[2] = {1.0f - xd, xd}, yw[2] = {1.0f - yd, yd}, zw[2] = {1.0f - zd, zd};
            int xs[2], ys[2], zs[2];
            xs[0] = max(0, min(255, (int)flx)); xs[1] = min(255, xs[0] + 1);
            ys[0] = max(0, min(255, (int)fly)); ys[1] = min(255, ys[0] + 1);
            zs[0] = max(0, min(255, (int)flz)); zs[1] = min(255, zs[0] + 1);
            int xm[2], xp[2], ym[2], yp[2], zm[2], zp[2];
#pragma unroll
            for (int a = 0; a < 2; a++) {
                xm[a] = max(xs[a] - 1, 0); xp[a] = min(xs[a] + 1, 255);
                ym[a] = max(ys[a] - 1, 0); yp[a] = min(ys[a] + 1, 255);
                zm[a] = max(zs[a] - 1, 0); zp[a] = min(zs[a] + 1, 255);
            }
            const float s = 63.75f;
            float r0 = 0.0f, r1 = 0.0f, r2 = 0.0f, r3 = 0.0f;
#pragma unroll
            for (int a = 0; a < 2; a++)
#pragma unroll
                for (int b = 0; b < 2; b++)
#pragma unroll
                    for (int cI = 0; cI < 2; cI++) {
                        int bx = xs[a] << 16, by = ys[b] << 8, bz = zs[cI];
                        float w  = xw[a] * yw[b] * zw[cI];
                        float v  = __ldg(grid + (bx | by | bz));
                        float gx = (__ldg(grid + ((xp[a] << 16) | by | bz)) -
                                    __ldg(grid + ((xm[a] << 16) | by | bz))) * s;
                        float gy = (__ldg(grid + (bx | (yp[b] << 8) | bz)) -
                                    __ldg(grid + (bx | (ym[b] << 8) | bz))) * s;
                        float gz = (__ldg(grid + (bx | by | zp[cI])) -
                                    __ldg(grid + (bx | by | zm[cI]))) * s;
                        r0 = fmaf(w, v,  r0);
                        r1 = fmaf(w, gx, r1);
                        r2 = fmaf(w, gy, r2);
                        r3 = fmaf(w, gz, r3);
                    }
            ((float4*)(smem + SM_RET))[tid] = make_float4(r0, r1, r2, r3);
        }

        // ---- feats (63 + zero pad) -> fp16 SMEM row ----
        {
            float f[64];
            f[0] = px; f[1] = py; f[2] = pz; f[63] = 0.0f;
            float s0, c0, s1, c1, s2, c2;
            __sincosf(px, &s0, &c0); __sincosf(py, &s1, &c1); __sincosf(pz, &s2, &c2);
#pragma unroll
            for (int b = 0; b < 10; b++) {
                f[3 + 6 * b + 0] = s0; f[3 + 6 * b + 1] = s1; f[3 + 6 * b + 2] = s2;
                f[3 + 6 * b + 3] = c0; f[3 + 6 * b + 4] = c1; f[3 + 6 * b + 5] = c2;
                float ns0 = 2.0f * s0 * c0, nc0 = 1.0f - 2.0f * s0 * s0;
                float ns1 = 2.0f * s1 * c1, nc1 = 1.0f - 2.0f * s1 * s1;
                float ns2 = 2.0f * s2 * c2, nc2 = 1.0f - 2.0f * s2 * s2;
                s0 = ns0; c0 = nc0; s1 = ns1; c1 = nc1; s2 = ns2; c2 = nc2;
            }
            u32* frow = (u32*)(smem + SM_FEAT + tid * 144);
#pragma unroll
            for (int j = 0; j < 32; j++) frow[j] = pkh2(f[2 * j], f[2 * j + 1]);
        }
        __syncwarp();   // FEAT/RET rows are warp-local: no CTA barrier needed

        u32 c[2][16][2];
        u32 A[2][8][4];

        // ---- layer 0: feats (4 kc) -> 128 ----
        {
            u32 AF[2][4][4];
#pragma unroll
            for (int mt = 0; mt < 2; mt++) {
                const __half* rp = FS + (row0 + 16 * mt) * FEAT_STRIDE + 2 * t4;
#pragma unroll
                for (int kc = 0; kc < 4; kc++) {
                    AF[mt][kc][0] = *(const u32*)(rp + kc * 16);
                    AF[mt][kc][1] = *(const u32*)(rp + kc * 16 + 8 * FEAT_STRIDE);
                    AF[mt][kc][2] = *(const u32*)(rp + kc * 16 + 8);
                    AF[mt][kc][3] = *(const u32*)(rp + kc * 16 + 8 * FEAT_STRIDE + 8);
                }
            }
            run_layer<4>(c, AF, W0, lane);
            epi_h2(c, BH, t4, A);
        }

        // ---- layers 1 & 2: 128 -> 128 ----
        run_layer<8>(c, A, W1, lane);
        epi_h2(c, BH + 128, t4, A);
        run_layer<8>(c, A, W2, lane);
        epi_h2(c, BH + 256, t4, A);

        // ---- layer 3: concat(h[128] = 8 kc, feats = 4 kc) -> 128 ----
        {
#pragma unroll
            for (int mt = 0; mt < 2; mt++)
#pragma unroll
                for (int n = 0; n < 16; n++) { c[mt][n][0] = 0u; c[mt][n][1] = 0u; }
#pragma unroll
            for (int kc = 0; kc < 8; kc++)
#pragma unroll
                for (int n = 0; n < 16; n++) {
                    uint2 b = W3[(kc * 16 + n) * 32 + lane];
                    mma_h16(c[0][n], A[0][kc], b.x, b.y);
                    mma_h16(c[1][n], A[1][kc], b.x, b.y);
                }
#pragma unroll
            for (int kc = 8; kc < 12; kc++) {
                u32 AF[2][4];
#pragma unroll
                for (int mt = 0; mt < 2; mt++) {
                    const __half* rp = FS + (row0 + 16 * mt) * FEAT_STRIDE
                                       + (kc - 8) * 16 + 2 * t4;
                    AF[mt][0] = *(const u32*)rp;
                    AF[mt][1] = *(const u32*)(rp + 8 * FEAT_STRIDE);
                    AF[mt][2] = *(const u32*)(rp + 8);
                    AF[mt][3] = *(const u32*)(rp + 8 * FEAT_STRIDE + 8);
                }
#pragma unroll
                for (int n = 0; n < 16; n++) {
                    uint2 b = W3[(kc * 16 + n) * 32 + lane];
                    mma_h16(c[0][n], AF[0], b.x, b.y);
                    mma_h16(c[1][n], AF[1], b.x, b.y);
                }
            }
        }

        // ---- bias+relu (f32), head, Rodrigues ----
        {
            float acc[2][16][4];
            const float* b3s = (const float*)(smem + PB3_OFF);
#pragma unroll
            for (int mt = 0; mt < 2; mt++)
#pragma unroll
                for (int n = 0; n < 16; n++) {
                    float2 bb = *(const float2*)(b3s + 8 * n + 2 * t4);
                    float2 lo = __half22float2(*(__half2*)&c[mt][n][0]);
                    float2 hi = __half22float2(*(__half2*)&c[mt][n][1]);
                    acc[mt][n][0] = fmaxf(lo.x + bb.x, 0.0f);
                    acc[mt][n][1] = fmaxf(lo.y + bb.y, 0.0f);
                    acc[mt][n][2] = fmaxf(hi.x + bb.x, 0.0f);
                    acc[mt][n][3] = fmaxf(hi.y + bb.y, 0.0f);
                }

            const float* wos = (const float*)(smem + PWO_OFF);
            float pd[2][2][3];
#pragma unroll
            for (int mt = 0; mt < 2; mt++)
#pragma unroll
                for (int hf = 0; hf < 2; hf++)
#pragma unroll
                    for (int j = 0; j < 3; j++) pd[mt][hf][j] = 0.0f;
#pragma unroll
            for (int n = 0; n < 16; n++) {
                int o = 8 * n + 2 * t4;
                float w00 = wos[3 * o],     w01 = wos[3 * o + 1], w02 = wos[3 * o + 2];
                float w10 = wos[3 * o + 3], w11 = wos[3 * o + 4], w12 = wos[3 * o + 5];
#pragma unroll
                for (int mt = 0; mt < 2; mt++) {
                    pd[mt][0][0] += acc[mt][n][0] * w00 + acc[mt][n][1] * w10;
                    pd[mt][0][1] += acc[mt][n][0] * w01 + acc[mt][n][1] * w11;
                    pd[mt][0][2] += acc[mt][n][0] * w02 + acc[mt][n][1] * w12;
                    pd[mt][1][0] += acc[mt][n][2] * w00 + acc[mt][n][3] * w10;
                    pd[mt][1][1] += acc[mt][n][2] * w01 + acc[mt][n][3] * w11;
                    pd[mt][1][2] += acc[mt][n][2] * w02 + acc[mt][n][3] * w12;
                }
            }
#pragma unroll
            for (int mt = 0; mt < 2; mt++)
#pragma unroll
                for (int hf = 0; hf < 2; hf++)
#pragma unroll
                    for (int j = 0; j < 3; j++) {
                        float v = pd[mt][hf][j];
                        v += __shfl_xor_sync(0xFFFFFFFF, v, 1);
                        v += __shfl_xor_sync(0xFFFFFFFF, v, 2);
                        pd[mt][hf][j] = v;
                    }
            if (t4 == 0) {
                const float* bos = (const float*)(smem + PBO_OFF);
#pragma unroll
                for (int mt = 0; mt < 2; mt++)
#pragma unroll
                    for (int hf = 0; hf < 2; hf++) {
                        int lp = 32 * wp + 16 * mt + lr + 8 * hf;
                        int gg = tile * PTS_PER_TILE + lp;
                        float r0 = pd[mt][hf][0] + bos[0];
                        float r1 = pd[mt][hf][1] + bos[1];
                        float r2 = pd[mt][hf][2] + bos[2];
                        float theta = sqrtf(r0 * r0 + r1 * r1 + r2 * r2 + 1e-12f);
                        float it = 1.0f / theta;
                        float e0 = r0 * it, e1 = r1 * it, e2 = r2 * it;
                        float4 ret = ((const float4*)(smem + SM_RET))[lp];
                        float cc0 = ret.y, cc1 = ret.z, cc2 = ret.w;
                        float a = sqrtf(cc0 * cc0 + cc1 * cc1 + cc2 * cc2 + 1e-12f);
                        float ia = 1.0f / a;
                        float v0 = cc0 * ia, v1 = cc1 * ia, v2 = cc2 * ia;
                        float ct = cosf(theta), st = sinf(theta);
                        float cr0 = e1 * v2 - e2 * v1;
                        float cr1 = e2 * v0 - e0 * v2;
                        float cr2 = e0 * v1 - e1 * v0;
                        float k1 = (1.0f - ct) * (e0 * v0 + e1 * v1 + e2 * v2);
                        if (gg < B) {
                            out[gg] = ret.x;
                            out[B + 3 * gg + 0] = cc0;
                            out[B + 3 * gg + 1] = cc1;
                            out[B + 3 * gg + 2] = cc2;
                            out[4 * B + 3 * gg + 0] = a * (ct * v0 + st * cr0 + k1 * e0);
                            out[4 * B + 3 * gg + 1] = a * (ct * v1 + st * cr1 + k1 * e1);
                            out[4 * B + 3 * gg + 2] = a * (ct * v2 + st * cr2 + k1 * e2);
                        }
                    }
            }
        }
        __syncwarp();   // warp-local FEAT/RET reuse protection for next tile
    }
}

// ---------------------------------------------------------------------------
extern "C" void kernel_launch(void* const* d_in, const int* in_sizes, int n_in,
                              void* d_out, int out_size) {
    const float* x    = (const float*)d_in[0];
    const float* grid = (const float*)d_in[1];
    const float* w0   = (const float*)d_in[2];
    const float* b0   = (const float*)d_in[3];
    const float* w1   = (const float*)d_in[4];
    const float* b1   = (const float*)d_in[5];
    const float* w2   = (const float*)d_in[6];
    const float* b2   = (const float*)d_in[7];
    const float* w3   = (const float*)d_in[8];
    const float* b3   = (const float*)d_in[9];
    const float* wo   = (const float*)d_in[10];
    const float* bo   = (const float*)d_in[11];
    float* out = (float*)d_out;
    int B = in_sizes[0] / 3;
    int ntiles = (B + PTS_PER_TILE - 1) / PTS_PER_TILE;

    cudaFuncSetAttribute(main_kernel,
                         cudaFuncAttributeMaxDynamicSharedMemorySize, SMEM_BYTES);

    prep_weights<<<68, 256>>>(w0, w1, w2, w3, b0, b1, b2, b3, wo, bo);
    main_kernel<<<148, THREADS, SMEM_BYTES>>>(x, grid, out, B, ntiles);
    (void)n_in; (void)out_size;
}

// round 15
// speedup vs baseline: 1.1584x; 1.1584x over previous
#include <cuda_runtime.h>
#include <cuda_fp16.h>

#define NTOT (256*256*256)
#define THREADS 384
#define PTS_PER_TILE 384

typedef unsigned int u32;

// ---------------- packed weight image (global + SMEM, same layout) ----------
// fp16 B-fragment order per layer: uint2 slot s = ((kc*16 + n)*32 + lane)
#define PW_L0    0          // 4 kc  -> 16384 B
#define PW_L1    16384      // 8 kc  -> 32768 B
#define PW_L2    49152      // 8 kc  -> 32768 B
#define PW_L3    81920      // 12 kc -> 49152 B
#define PBH_OFF  131072     // b0,b1,b2 as fp16
#define PB3_OFF  132096     // b3 f32
#define PWO_OFF  132608     // 384 f32
#define PBO_OFF  134144     // 3 f32 (+pad)
#define COPY_BYTES 134160
#define COPY_U4  (COPY_BYTES/16)

// SMEM extras
#define SM_FEAT  COPY_BYTES                      // 384 rows x 144 B (64 fp16 + pad)
#define FEAT_STRIDE 72                           // halves per row
#define SM_RET   (SM_FEAT + PTS_PER_TILE*144)
#define SMEM_BYTES (SM_RET + PTS_PER_TILE*16)    // 195600 B

__device__ float4 g_data[NTOT];                               // grid value + gradient
__device__ __align__(16) unsigned char g_wpack[COPY_BYTES];   // packed weights image

static __device__ __forceinline__ u32 pkh2(float lo, float hi) {
    __half2 h = __floats2half2_rn(lo, hi);
    return *(u32*)&h;
}
static __device__ __forceinline__ u32 relu_bias_h2(u32 c, u32 b) {
    __half2 z = __floats2half2_rn(0.0f, 0.0f);
    __half2 r = __hmax2(__hadd2(*(__half2*)&c, *(__half2*)&b), z);
    return *(u32*)&r;
}

static __device__ __forceinline__ void mma_h16(u32 c[2], const u32 a[4], u32 b0, u32 b1) {
    asm("mma.sync.aligned.m16n8k16.row.col.f16.f16.f16.f16 "
        "{%0,%1}, {%2,%3,%4,%5}, {%6,%7}, {%0,%1};"
        : "+r"(c[0]), "+r"(c[1])
        : "r"(a[0]), "r"(a[1]), "r"(a[2]), "r"(a[3]), "r"(b0), "r"(b1));
}

// ---------------------------------------------------------------------------
// Kernel 1: grid value + central-difference gradient (exact fp32)
// ---------------------------------------------------------------------------
__global__ void grad_kernel(const float* __restrict__ g) {
    int i = blockIdx.x * 256 + threadIdx.x;
    int iz = i & 255, iy = (i >> 8) & 255, ix = i >> 16;
    float c  = __ldg(g + i);
    float xp = __ldg(g + (ix < 255 ? i + 65536 : i));
    float xm = __ldg(g + (ix > 0   ? i - 65536 : i));
    float yp = __ldg(g + (iy < 255 ? i + 256 : i));
    float ym = __ldg(g + (iy > 0   ? i - 256 : i));
    float zp = __ldg(g + (iz < 255 ? i + 1 : i));
    float zm = __ldg(g + (iz > 0   ? i - 1 : i));
    const float s = 63.75f;
    g_data[i] = make_float4(c, (xp - xm) * s, (yp - ym) * s, (zp - zm) * s);
}

// ---------------------------------------------------------------------------
// Kernel 2: pack weights into fp16 B-fragment order.
// ---------------------------------------------------------------------------
__global__ void prep_weights(const float* __restrict__ w0, const float* __restrict__ w1,
                             const float* __restrict__ w2, const float* __restrict__ w3,
                             const float* __restrict__ b0, const float* __restrict__ b1,
                             const float* __restrict__ b2, const float* __restrict__ b3,
                             const float* __restrict__ wo, const float* __restrict__ bo) {
    int t = blockIdx.x * 256 + threadIdx.x;
    if (t < 16384) {
        const float* w; int Kreal, base, s;
        if      (t < 2048)  { w = w0; Kreal = 63;  base = PW_L0; s = t; }
        else if (t < 6144)  { w = w1; Kreal = 128; base = PW_L1; s = t - 2048; }
        else if (t < 10240) { w = w2; Kreal = 128; base = PW_L2; s = t - 6144; }
        else                { w = w3; Kreal = 191; base = PW_L3; s = t - 10240; }
        int lane = s & 31, n = (s >> 5) & 15, kc = s >> 9;
        int k0 = kc * 16 + (lane & 3) * 2;
        int o  = n * 8 + (lane >> 2);
        float v00 = (k0     < Kreal) ? __ldg(w + (k0    ) * 128 + o) : 0.0f;
        float v01 = (k0 + 1 < Kreal) ? __ldg(w + (k0 + 1) * 128 + o) : 0.0f;
        float v10 = (k0 + 8 < Kreal) ? __ldg(w + (k0 + 8) * 128 + o) : 0.0f;
        float v11 = (k0 + 9 < Kreal) ? __ldg(w + (k0 + 9) * 128 + o) : 0.0f;
        ((uint2*)(g_wpack + base))[s] = make_uint2(pkh2(v00, v01), pkh2(v10, v11));
    } else if (t < 16768) {
        int j = t - 16384;
        const float* bs = (j < 128) ? b0 : (j < 256) ? b1 : b2;
        *(__half*)(g_wpack + PBH_OFF + j * 2) = __float2half_rn(__ldg(bs + (j & 127)));
    } else if (t < 16896) {
        int j = t - 16768;
        *(float*)(g_wpack + PB3_OFF + j * 4) = __ldg(b3 + j);
    } else if (t < 17280) {
        int j = t - 16896;
        *(float*)(g_wpack + PWO_OFF + j * 4) = __ldg(wo + j);
    } else if (t < 17283) {
        int j = t - 17280;
        *(float*)(g_wpack + PBO_OFF + j * 4) = __ldg(bo + j);
    }
}

// ---------------------------------------------------------------------------
// Epilogue: C frags + bias(fp16) -> relu -> next-layer A frags (register-only)
// ---------------------------------------------------------------------------
static __device__ __forceinline__ void epi_h2(const u32 c[2][16][2],
                                              const __half* __restrict__ bh,
                                              int t4, u32 A[2][8][4]) {
#pragma unroll
    for (int mt = 0; mt < 2; mt++)
#pragma unroll
        for (int n = 0; n < 16; n++) {
            u32 bb = *(const u32*)(bh + 8 * n + 2 * t4);
            A[mt][n >> 1][(n & 1) * 2 + 0] = relu_bias_h2(c[mt][n][0], bb);
            A[mt][n >> 1][(n & 1) * 2 + 1] = relu_bias_h2(c[mt][n][1], bb);
        }
}

template <int CH>
static __device__ __forceinline__ void run_layer(u32 c[2][16][2],
                                                 const u32 A[2][CH][4],
                                                 const uint2* __restrict__ W, int lane) {
#pragma unroll
    for (int mt = 0; mt < 2; mt++)
#pragma unroll
        for (int n = 0; n < 16; n++) { c[mt][n][0] = 0u; c[mt][n][1] = 0u; }
#pragma unroll
    for (int kc = 0; kc < CH; kc++)
#pragma unroll
        for (int n = 0; n < 16; n++) {
            uint2 b = W[(kc * 16 + n) * 32 + lane];
            mma_h16(c[0][n], A[0][kc], b.x, b.y);
            mma_h16(c[1][n], A[1][kc], b.x, b.y);
        }
}

// ---------------------------------------------------------------------------
// Main fused persistent kernel: 384 threads = 12 warps, 32 points/warp/tile.
// All per-tile SMEM (FEAT rows, RET entries) is warp-local -> no CTA barriers
// inside the tile loop; warps run mutually desynchronized so one warp's
// DRAM gather overlaps another warp's HMMA stream.
// ---------------------------------------------------------------------------
__global__ void __launch_bounds__(THREADS, 1)
main_kernel(const float* __restrict__ x, float* __restrict__ out, int B, int ntiles) {
    extern __shared__ unsigned char smem[];
    int tid = threadIdx.x;
    int lane = tid & 31, wp = tid >> 5;
    int t4 = lane & 3, lr = lane >> 2;

    // ---- one-time weight image copy L2 -> SMEM ----
    {
        const uint4* s = (const uint4*)g_wpack;
        uint4* d = (uint4*)smem;
#pragma unroll 4
        for (int i = tid; i < COPY_U4; i += THREADS) d[i] = s[i];
    }
    __syncthreads();

    const __half* FS = (const __half*)(smem + SM_FEAT);
    const __half* BH = (const __half*)(smem + PBH_OFF);
    const uint2* W0 = (const uint2*)(smem + PW_L0);
    const uint2* W1 = (const uint2*)(smem + PW_L1);
    const uint2* W2 = (const uint2*)(smem + PW_L2);
    const uint2* W3 = (const uint2*)(smem + PW_L3);
    int row0 = 32 * wp + lr;      // m-tile 0 base row

    for (int tile = blockIdx.x; tile < ntiles; tile += gridDim.x) {
        int gi = tile * PTS_PER_TILE + tid;
        int gc = min(gi, B - 1);
        float px = __ldg(x + 3 * gc), py = __ldg(x + 3 * gc + 1), pz = __ldg(x + 3 * gc + 2);

        // ---- trilinear (exact fp32) -> RET smem ----
        {
            float fx = (px + 1.0f) * 127.5f, fy = (py + 1.0f) * 127.5f, fz = (pz + 1.0f) * 127.5f;
            float flx = floorf(fx), fly = floorf(fy), flz = floorf(fz);
            float xd = fx - flx, yd = fy - fly, zd = fz - flz;
            int x0 = max(0, min(255, (int)flx)), x1 = max(0, min(255, (int)flx + 1));
            int y0 = max(0, min(255, (int)fly)), y1 = max(0, min(255, (int)fly + 1));
            int z0 = max(0, min(255, (int)flz)), z1 = max(0, min(255, (int)flz + 1));
            int bx0 = x0 << 16, bx1 = x1 << 16, by0 = y0 << 8, by1 = y1 << 8;
            float4 c000 = g_data[bx0 + by0 + z0], c100 = g_data[bx1 + by0 + z0];
            float4 c010 = g_data[bx0 + by1 + z0], c110 = g_data[bx1 + by1 + z0];
            float4 c001 = g_data[bx0 + by0 + z1], c101 = g_data[bx1 + by0 + z1];
            float4 c011 = g_data[bx0 + by1 + z1], c111 = g_data[bx1 + by1 + z1];
            float xu = 1.0f - xd, yu = 1.0f - yd, zu = 1.0f - zd;
            float a0x = c000.x * xu + c100.x * xd, a0y = c000.y * xu + c100.y * xd,
                  a0z = c000.z * xu + c100.z * xd, a0w = c000.w * xu + c100.w * xd;
            float b0x = c010.x * xu + c110.x * xd, b0y = c010.y * xu + c110.y * xd,
                  b0z = c010.z * xu + c110.z * xd, b0w = c010.w * xu + c110.w * xd;
            float a1x = c001.x * xu + c101.x * xd, a1y = c001.y * xu + c101.y * xd,
                  a1z = c001.z * xu + c101.z * xd, a1w = c001.w * xu + c101.w * xd;
            float b1x = c011.x * xu + c111.x * xd, b1y = c011.y * xu + c111.y * xd,
                  b1z = c011.z * xu + c111.z * xd, b1w = c011.w * xu + c111.w * xd;
            float e0x = a0x * yu + b0x * yd, e0y = a0y * yu + b0y * yd,
                  e0z = a0z * yu + b0z * yd, e0w = a0w * yu + b0w * yd;
            float e1x = a1x * yu + b1x * yd, e1y = a1y * yu + b1y * yd,
                  e1z = a1z * yu + b1z * yd, e1w = a1w * yu + b1w * yd;
            ((float4*)(smem + SM_RET))[tid] =
                make_float4(e0x * zu + e1x * zd, e0y * zu + e1y * zd,
                            e0z * zu + e1z * zd, e0w * zu + e1w * zd);
        }

        // ---- feats (63 + zero pad) -> fp16 SMEM row ----
        {
            float f[64];
            f[0] = px; f[1] = py; f[2] = pz; f[63] = 0.0f;
            float s0, c0, s1, c1, s2, c2;
            __sincosf(px, &s0, &c0); __sincosf(py, &s1, &c1); __sincosf(pz, &s2, &c2);
#pragma unroll
            for (int b = 0; b < 10; b++) {
                f[3 + 6 * b + 0] = s0; f[3 + 6 * b + 1] = s1; f[3 + 6 * b + 2] = s2;
                f[3 + 6 * b + 3] = c0; f[3 + 6 * b + 4] = c1; f[3 + 6 * b + 5] = c2;
                float ns0 = 2.0f * s0 * c0, nc0 = 1.0f - 2.0f * s0 * s0;
                float ns1 = 2.0f * s1 * c1, nc1 = 1.0f - 2.0f * s1 * s1;
                float ns2 = 2.0f * s2 * c2, nc2 = 1.0f - 2.0f * s2 * s2;
                s0 = ns0; c0 = nc0; s1 = ns1; c1 = nc1; s2 = ns2; c2 = nc2;
            }
            u32* frow = (u32*)(smem + SM_FEAT + tid * 144);
#pragma unroll
            for (int j = 0; j < 32; j++) frow[j] = pkh2(f[2 * j], f[2 * j + 1]);
        }
        __syncwarp();   // FEAT/RET rows are warp-local: no CTA barrier needed

        u32 c[2][16][2];
        u32 A[2][8][4];

        // ---- layer 0: feats (4 kc) -> 128 ----
        {
            u32 AF[2][4][4];
#pragma unroll
            for (int mt = 0; mt < 2; mt++) {
                const __half* rp = FS + (row0 + 16 * mt) * FEAT_STRIDE + 2 * t4;
#pragma unroll
                for (int kc = 0; kc < 4; kc++) {
                    AF[mt][kc][0] = *(const u32*)(rp + kc * 16);
                    AF[mt][kc][1] = *(const u32*)(rp + kc * 16 + 8 * FEAT_STRIDE);
                    AF[mt][kc][2] = *(const u32*)(rp + kc * 16 + 8);
                    AF[mt][kc][3] = *(const u32*)(rp + kc * 16 + 8 * FEAT_STRIDE + 8);
                }
            }
            run_layer<4>(c, AF, W0, lane);
            epi_h2(c, BH, t4, A);
        }

        // ---- layers 1 & 2: 128 -> 128 ----
        run_layer<8>(c, A, W1, lane);
        epi_h2(c, BH + 128, t4, A);
        run_layer<8>(c, A, W2, lane);
        epi_h2(c, BH + 256, t4, A);

        // ---- layer 3: concat(h[128] = 8 kc, feats = 4 kc) -> 128 ----
        {
#pragma unroll
            for (int mt = 0; mt < 2; mt++)
#pragma unroll
                for (int n = 0; n < 16; n++) { c[mt][n][0] = 0u; c[mt][n][1] = 0u; }
#pragma unroll
            for (int kc = 0; kc < 8; kc++)
#pragma unroll
                for (int n = 0; n < 16; n++) {
                    uint2 b = W3[(kc * 16 + n) * 32 + lane];
                    mma_h16(c[0][n], A[0][kc], b.x, b.y);
                    mma_h16(c[1][n], A[1][kc], b.x, b.y);
                }
#pragma unroll
            for (int kc = 8; kc < 12; kc++) {
                u32 AF[2][4];
#pragma unroll
                for (int mt = 0; mt < 2; mt++) {
                    const __half* rp = FS + (row0 + 16 * mt) * FEAT_STRIDE
                                       + (kc - 8) * 16 + 2 * t4;
                    AF[mt][0] = *(const u32*)rp;
                    AF[mt][1] = *(const u32*)(rp + 8 * FEAT_STRIDE);
                    AF[mt][2] = *(const u32*)(rp + 8);
                    AF[mt][3] = *(const u32*)(rp + 8 * FEAT_STRIDE + 8);
                }
#pragma unroll
                for (int n = 0; n < 16; n++) {
                    uint2 b = W3[(kc * 16 + n) * 32 + lane];
                    mma_h16(c[0][n], AF[0], b.x, b.y);
                    mma_h16(c[1][n], AF[1], b.x, b.y);
                }
            }
        }

        // ---- bias+relu (f32), head, Rodrigues ----
        {
            float acc[2][16][4];
            const float* b3s = (const float*)(smem + PB3_OFF);
#pragma unroll
            for (int mt = 0; mt < 2; mt++)
#pragma unroll
                for (int n = 0; n < 16; n++) {
                    float2 bb = *(const float2*)(b3s + 8 * n + 2 * t4);
                    float2 lo = __half22float2(*(__half2*)&c[mt][n][0]);
                    float2 hi = __half22float2(*(__half2*)&c[mt][n][1]);
                    acc[mt][n][0] = fmaxf(lo.x + bb.x, 0.0f);
                    acc[mt][n][1] = fmaxf(lo.y + bb.y, 0.0f);
                    acc[mt][n][2] = fmaxf(hi.x + bb.x, 0.0f);
                    acc[mt][n][3] = fmaxf(hi.y + bb.y, 0.0f);
                }

            const float* wos = (const float*)(smem + PWO_OFF);
            float pd[2][2][3];
#pragma unroll
            for (int mt = 0; mt < 2; mt++)
#pragma unroll
                for (int hf = 0; hf < 2; hf++)
#pragma unroll
                    for (int j = 0; j < 3; j++) pd[mt][hf][j] = 0.0f;
#pragma unroll
            for (int n = 0; n < 16; n++) {
                int o = 8 * n + 2 * t4;
                float w00 = wos[3 * o],     w01 = wos[3 * o + 1], w02 = wos[3 * o + 2];
                float w10 = wos[3 * o + 3], w11 = wos[3 * o + 4], w12 = wos[3 * o + 5];
#pragma unroll
                for (int mt = 0; mt < 2; mt++) {
                    pd[mt][0][0] += acc[mt][n][0] * w00 + acc[mt][n][1] * w10;
                    pd[mt][0][1] += acc[mt][n][0] * w01 + acc[mt][n][1] * w11;
                    pd[mt][0][2] += acc[mt][n][0] * w02 + acc[mt][n][1] * w12;
                    pd[mt][1][0] += acc[mt][n][2] * w00 + acc[mt][n][3] * w10;
                    pd[mt][1][1] += acc[mt][n][2] * w01 + acc[mt][n][3] * w11;
                    pd[mt][1][2] += acc[mt][n][2] * w02 + acc[mt][n][3] * w12;
                }
            }
#pragma unroll
            for (int mt = 0; mt < 2; mt++)
#pragma unroll
                for (int hf = 0; hf < 2; hf++)
#pragma unroll
                    for (int j = 0; j < 3; j++) {
                        float v = pd[mt][hf][j];
                        v += __shfl_xor_sync(0xFFFFFFFF, v, 1);
                        v += __shfl_xor_sync(0xFFFFFFFF, v, 2);
                        pd[mt][hf][j] = v;
                    }
            if (t4 == 0) {
                const float* bos = (const float*)(smem + PBO_OFF);
#pragma unroll
                for (int mt = 0; mt < 2; mt++)
#pragma unroll
                    for (int hf = 0; hf < 2; hf++) {
                        int lp = 32 * wp + 16 * mt + lr + 8 * hf;
                        int gg = tile * PTS_PER_TILE + lp;
                        float r0 = pd[mt][hf][0] + bos[0];
                        float r1 = pd[mt][hf][1] + bos[1];
                        float r2 = pd[mt][hf][2] + bos[2];
                        float theta = sqrtf(r0 * r0 + r1 * r1 + r2 * r2 + 1e-12f);
                        float it = 1.0f / theta;
                        float e0 = r0 * it, e1 = r1 * it, e2 = r2 * it;
                        float4 ret = ((const float4*)(smem + SM_RET))[lp];
                        float cc0 = ret.y, cc1 = ret.z, cc2 = ret.w;
                        float a = sqrtf(cc0 * cc0 + cc1 * cc1 + cc2 * cc2 + 1e-12f);
                        float ia = 1.0f / a;
                        float v0 = cc0 * ia, v1 = cc1 * ia, v2 = cc2 * ia;
                        float ct = cosf(theta), st = sinf(theta);
                        float cr0 = e1 * v2 - e2 * v1;
                        float cr1 = e2 * v0 - e0 * v2;
                        float cr2 = e0 * v1 - e1 * v0;
                        float k1 = (1.0f - ct) * (e0 * v0 + e1 * v1 + e2 * v2);
                        if (gg < B) {
                            out[gg] = ret.x;
                            out[B + 3 * gg + 0] = cc0;
                            out[B + 3 * gg + 1] = cc1;
                            out[B + 3 * gg + 2] = cc2;
                            out[4 * B + 3 * gg + 0] = a * (ct * v0 + st * cr0 + k1 * e0);
                            out[4 * B + 3 * gg + 1] = a * (ct * v1 + st * cr1 + k1 * e1);
                            out[4 * B + 3 * gg + 2] = a * (ct * v2 + st * cr2 + k1 * e2);
                        }
                    }
            }
        }
        __syncwarp();   // warp-local FEAT/RET reuse protection for next tile
    }
}

// ---------------------------------------------------------------------------
extern "C" void kernel_launch(void* const* d_in, const int* in_sizes, int n_in,
                              void* d_out, int out_size) {
    const float* x    = (const float*)d_in[0];
    const float* grid = (const float*)d_in[1];
    const float* w0   = (const float*)d_in[2];
    const float* b0   = (const float*)d_in[3];
    const float* w1   = (const float*)d_in[4];
    const float* b1   = (const float*)d_in[5];
    const float* w2   = (const float*)d_in[6];
    const float* b2   = (const float*)d_in[7];
    const float* w3   = (const float*)d_in[8];
    const float* b3   = (const float*)d_in[9];
    const float* wo   = (const float*)d_in[10];
    const float* bo   = (const float*)d_in[11];
    float* out = (float*)d_out;
    int B = in_sizes[0] / 3;
    int ntiles = (B + PTS_PER_TILE - 1) / PTS_PER_TILE;

    cudaFuncSetAttribute(main_kernel,
                         cudaFuncAttributeMaxDynamicSharedMemorySize, SMEM_BYTES);

    grad_kernel<<<NTOT / 256, 256>>>(grid);
    prep_weights<<<68, 256>>>(w0, w1, w2, w3, b0, b1, b2, b3, wo, bo);
    main_kernel<<<148, THREADS, SMEM_BYTES>>>(x, out, B, ntiles);
    (void)n_in; (void)out_size;
}